// round 1
// baseline (speedup 1.0000x reference)
#include <cuda_runtime.h>
#include <cuda_bf16.h>
#include <math.h>

#define S    100
#define Bsz  128
#define NW   430500
#define NB   580
// weight offsets within a sample's NW block
#define W1_OFF 0        // [20][1][5][5]  = 500
#define W2_OFF 500      // [50][20][5][5] = 25000
#define W3_OFF 25500    // [500][800]     = 400000
#define W4_OFF 425500   // [10][500]      = 5000
// bias offsets within a sample's NB block
#define B1_OFF 0
#define B2_OFF 20
#define B3_OFF 70
#define B4_OFF 570

// ---------------- device scratch (allocation-free contract) ----------------
__device__ float g_w[(size_t)S * NW];          // 172 MB materialized weights
__device__ float g_b[(size_t)S * NB];
__device__ float g_h1[(size_t)S * Bsz * 20 * 12 * 12];   // 147 MB
__device__ float g_h2[(size_t)S * Bsz * 800];            // 41 MB
__device__ float g_h3[(size_t)S * Bsz * 500];            // 26 MB
__device__ float g_logits[(size_t)Bsz * S * 10];         // 5 MB, [b][s][10]

// ---------------- K1: w = mu + softplus(rho)*e -----------------------------
__global__ void k_wgen(const float* __restrict__ e,
                       const float* __restrict__ mu_w, const float* __restrict__ rho_w,
                       const float* __restrict__ mu_b, const float* __restrict__ rho_b) {
    int i = blockIdx.x * blockDim.x + threadIdx.x;   // 0 .. NW+NB-1
    int s = blockIdx.y;
    if (i >= NW + NB) return;
    float ev = e[(size_t)s * (NW + NB) + i];
    if (i < NW) {
        g_w[(size_t)s * NW + i] = mu_w[i] + log1pf(expf(rho_w[i])) * ev;
    } else {
        int j = i - NW;
        g_b[s * NB + j] = mu_b[j] + log1pf(expf(rho_b[j])) * ev;
    }
}

// ---------------- K2: conv1 (1->20, 5x5) + relu + maxpool 2x2 --------------
// block = (b, s), 256 threads; 240 active: thread = (c in [0,20), py in [0,12))
// Each thread computes one pooled output row (12 px) of one channel via
// sliding-window register reuse: weights in regs, image rows in regs.
__global__ void k_conv1(const float* __restrict__ x) {
    __shared__ __align__(16) float img[784];
    __shared__ float w1s[500];
    __shared__ float b1s[20];
    int b = blockIdx.x, s = blockIdx.y;
    int tid = threadIdx.x;
    const float* xim = x + (size_t)b * 784;
    for (int k = tid; k < 784; k += 256) img[k] = xim[k];
    const float* wp = g_w + (size_t)s * NW + W1_OFF;
    for (int k = tid; k < 500; k += 256) w1s[k] = wp[k];
    if (tid < 20) b1s[tid] = g_b[s * NB + B1_OFF + tid];
    __syncthreads();
    if (tid >= 240) return;
    int c = tid / 12, py = tid % 12;
    float wr[25];
#pragma unroll
    for (int k = 0; k < 25; k++) wr[k] = w1s[c * 25 + k];
    float p[12];
#pragma unroll
    for (int px = 0; px < 12; px++) p[px] = -1e30f;
#pragma unroll
    for (int dy = 0; dy < 2; dy++) {
        int y = 2 * py + dy;
        float acc[24];
#pragma unroll
        for (int xx = 0; xx < 24; xx++) acc[xx] = 0.f;
#pragma unroll
        for (int i = 0; i < 5; i++) {
            const float* row = &img[(y + i) * 28];
            float r[28];
#pragma unroll
            for (int q = 0; q < 7; q++) {
                float4 v = *(const float4*)&row[q * 4];
                r[q * 4 + 0] = v.x; r[q * 4 + 1] = v.y;
                r[q * 4 + 2] = v.z; r[q * 4 + 3] = v.w;
            }
#pragma unroll
            for (int j = 0; j < 5; j++) {
                float wv = wr[i * 5 + j];
#pragma unroll
                for (int xx = 0; xx < 24; xx++) acc[xx] = fmaf(wv, r[xx + j], acc[xx]);
            }
        }
#pragma unroll
        for (int px = 0; px < 12; px++)
            p[px] = fmaxf(p[px], fmaxf(acc[2 * px], acc[2 * px + 1]));
    }
    float bias = b1s[c];
    float* out = g_h1 + ((size_t)(s * Bsz + b) * 20 + c) * 144 + py * 12;
#pragma unroll
    for (int px = 0; px < 12; px++) out[px] = fmaxf(p[px] + bias, 0.f);
}

// ---------------- K3: conv2 (20->50, 5x5) + relu + maxpool 2x2 -------------
// block = (image-group of 8, s), 320 threads, dynamic smem:
//   w2s[25000] | b2s[56] | h1s[4][2880] | cbuf[4][3200]
// 4 images in flight, 2 rounds. Per image: 80 threads = (cg in [0,10): 5 ch, y in [0,8)).
// Thread computes a 5ch x 8px conv row with register sliding window (~5.4 FMA/LDS-float).
#define C2_SMEM_FLOATS (25000 + 56 + 4*2880 + 4*3200)
__global__ void k_conv2() {
    extern __shared__ __align__(16) float smem[];
    float* w2s = smem;
    float* b2s = smem + 25000;
    float* h1s = b2s + 56;            // offset 25056 floats (16B aligned)
    float* cbuf = h1s + 4 * 2880;
    int s = blockIdx.y;
    int b0 = blockIdx.x * 8;
    int tid = threadIdx.x;            // 320
    const float* wp = g_w + (size_t)s * NW + W2_OFF;
    for (int k = tid; k < 25000; k += 320) w2s[k] = wp[k];
    if (tid < 50) b2s[tid] = g_b[s * NB + B2_OFF + tid];
    int il = tid / 80, r = tid % 80, cg = r / 8, y = r % 8;
    int c0 = cg * 5;
    for (int round = 0; round < 2; round++) {
        __syncthreads();   // weights ready (round 0) / buffers free (round 1)
        for (int k = tid; k < 4 * 2880; k += 320) {
            int i2 = k / 2880, kk = k % 2880;
            h1s[k] = g_h1[(size_t)(s * Bsz + b0 + round * 4 + i2) * 2880 + kk];
        }
        __syncthreads();
        float acc[5][8];
#pragma unroll
        for (int c = 0; c < 5; c++)
#pragma unroll
            for (int xx = 0; xx < 8; xx++) acc[c][xx] = 0.f;
        const float* hin = &h1s[il * 2880];
        for (int ci = 0; ci < 20; ci++) {
#pragma unroll
            for (int i = 0; i < 5; i++) {
                const float* rp = &hin[ci * 144 + (y + i) * 12];
                float rin[12];
#pragma unroll
                for (int q = 0; q < 3; q++) {
                    float4 v = *(const float4*)&rp[q * 4];
                    rin[q * 4 + 0] = v.x; rin[q * 4 + 1] = v.y;
                    rin[q * 4 + 2] = v.z; rin[q * 4 + 3] = v.w;
                }
#pragma unroll
                for (int j = 0; j < 5; j++) {
#pragma unroll
                    for (int c = 0; c < 5; c++) {
                        float wv = w2s[((c0 + c) * 20 + ci) * 25 + i * 5 + j];
#pragma unroll
                        for (int xx = 0; xx < 8; xx++)
                            acc[c][xx] = fmaf(wv, rin[xx + j], acc[c][xx]);
                    }
                }
            }
        }
#pragma unroll
        for (int c = 0; c < 5; c++) {
            float bias = b2s[c0 + c];
#pragma unroll
            for (int xx = 0; xx < 8; xx++)
                cbuf[il * 3200 + (c0 + c) * 64 + y * 8 + xx] = fmaxf(acc[c][xx] + bias, 0.f);
        }
        __syncthreads();
        for (int k = tid; k < 4 * 800; k += 320) {
            int i2 = k / 800, q = k % 800;
            int c = q / 16, p = q % 16, py = p / 4, px = p % 4;
            const float* cb = &cbuf[i2 * 3200 + c * 64];
            float v = fmaxf(fmaxf(cb[(2 * py) * 8 + 2 * px],     cb[(2 * py) * 8 + 2 * px + 1]),
                            fmaxf(cb[(2 * py + 1) * 8 + 2 * px], cb[(2 * py + 1) * 8 + 2 * px + 1]));
            g_h2[(size_t)(s * Bsz + b0 + round * 4 + i2) * 800 + q] = v;
        }
    }
}

// ---------------- K4: fc1 (800 -> 500) + relu, batched GEMM per sample -----
// block = (b-tile 64, o-tile 64, s), 256 threads, 4x4 register tile, K-chunks of 16.
__global__ void k_fc1() {
    __shared__ float As[64][17];
    __shared__ float Ws[64][17];
    int b0 = blockIdx.x * 64;
    int o0 = blockIdx.y * 64;
    int s  = blockIdx.z;
    int tid = threadIdx.x;
    int row = tid / 4, q = tid % 4;
    int ty = tid / 16, tx = tid % 16;
    float acc[4][4];
#pragma unroll
    for (int i = 0; i < 4; i++)
#pragma unroll
        for (int j = 0; j < 4; j++) acc[i][j] = 0.f;
    const float* h2p = g_h2 + (size_t)s * Bsz * 800;
    const float* w3p = g_w + (size_t)s * NW + W3_OFF;
    for (int k0 = 0; k0 < 800; k0 += 16) {
        float4 a = *(const float4*)&h2p[(b0 + row) * 800 + k0 + q * 4];
        As[row][q * 4 + 0] = a.x; As[row][q * 4 + 1] = a.y;
        As[row][q * 4 + 2] = a.z; As[row][q * 4 + 3] = a.w;
        int oo = o0 + row;
        float4 w = (oo < 500) ? *(const float4*)&w3p[(size_t)oo * 800 + k0 + q * 4]
                              : make_float4(0.f, 0.f, 0.f, 0.f);
        Ws[row][q * 4 + 0] = w.x; Ws[row][q * 4 + 1] = w.y;
        Ws[row][q * 4 + 2] = w.z; Ws[row][q * 4 + 3] = w.w;
        __syncthreads();
#pragma unroll
        for (int kk = 0; kk < 16; kk++) {
            float av[4], wv[4];
#pragma unroll
            for (int i = 0; i < 4; i++) av[i] = As[ty * 4 + i][kk];
#pragma unroll
            for (int j = 0; j < 4; j++) wv[j] = Ws[tx * 4 + j][kk];
#pragma unroll
            for (int i = 0; i < 4; i++)
#pragma unroll
                for (int j = 0; j < 4; j++) acc[i][j] = fmaf(av[i], wv[j], acc[i][j]);
        }
        __syncthreads();
    }
#pragma unroll
    for (int j = 0; j < 4; j++) {
        int o = o0 + tx * 4 + j;
        if (o < 500) {
            float bias = g_b[s * NB + B3_OFF + o];
#pragma unroll
            for (int i = 0; i < 4; i++) {
                int b = b0 + ty * 4 + i;
                g_h3[(size_t)(s * Bsz + b) * 500 + o] = fmaxf(acc[i][j] + bias, 0.f);
            }
        }
    }
}

// ---------------- K5: fc2 (500 -> 10) logits -------------------------------
// block = (b, s), 320 threads: warp w computes output o=w via warp-reduced dot.
__global__ void k_fc2() {
    int b = blockIdx.x, s = blockIdx.y;
    int w = threadIdx.x / 32, lane = threadIdx.x % 32;
    const float* h3p = g_h3 + (size_t)(s * Bsz + b) * 500;
    const float* w4p = g_w + (size_t)s * NW + W4_OFF + w * 500;
    float sum = 0.f;
    for (int k = lane; k < 500; k += 32) sum = fmaf(h3p[k], w4p[k], sum);
#pragma unroll
    for (int off = 16; off > 0; off >>= 1)
        sum += __shfl_down_sync(0xFFFFFFFF, sum, off);
    if (lane == 0)
        g_logits[((size_t)b * S + s) * 10 + w] = sum + g_b[s * NB + B4_OFF + w];
}

// ---------------- K6: log_softmax over 10, mean over S ---------------------
__global__ void k_reduce(float* __restrict__ out) {
    __shared__ float red[128][10];
    int b = blockIdx.x;
    int tid = threadIdx.x;   // 128
    if (tid < S) {
        const float* lp = g_logits + ((size_t)b * S + tid) * 10;
        float l[10], m = -1e30f;
#pragma unroll
        for (int o = 0; o < 10; o++) { l[o] = lp[o]; m = fmaxf(m, l[o]); }
        float se = 0.f;
#pragma unroll
        for (int o = 0; o < 10; o++) se += expf(l[o] - m);
        float lse = m + logf(se);
#pragma unroll
        for (int o = 0; o < 10; o++) red[tid][o] = l[o] - lse;
    } else {
#pragma unroll
        for (int o = 0; o < 10; o++) red[tid][o] = 0.f;
    }
    __syncthreads();
    for (int st = 64; st >= 1; st >>= 1) {
        if (tid < st)
#pragma unroll
            for (int o = 0; o < 10; o++) red[tid][o] += red[tid + st][o];
        __syncthreads();
    }
    if (tid < 10) out[b * 10 + tid] = red[0][tid] * (1.f / S);
}

// ---------------- launch ----------------------------------------------------
extern "C" void kernel_launch(void* const* d_in, const int* in_sizes, int n_in,
                              void* d_out, int out_size) {
    const float* x     = (const float*)d_in[0];
    const float* e     = (const float*)d_in[1];
    const float* mu_w  = (const float*)d_in[2];
    const float* rho_w = (const float*)d_in[3];
    const float* mu_b  = (const float*)d_in[4];
    const float* rho_b = (const float*)d_in[5];
    float* out = (float*)d_out;

    static bool attr_set = false;
    if (!attr_set) {
        cudaFuncSetAttribute(k_conv2, cudaFuncAttributeMaxDynamicSharedMemorySize,
                             C2_SMEM_FLOATS * (int)sizeof(float));
        attr_set = true;
    }

    // K1: weight materialization
    {
        dim3 grid((NW + NB + 255) / 256, S);
        k_wgen<<<grid, 256>>>(e, mu_w, rho_w, mu_b, rho_b);
    }
    // K2: conv1 + relu + pool
    {
        dim3 grid(Bsz, S);
        k_conv1<<<grid, 256>>>(x);
    }
    // K3: conv2 + relu + pool
    {
        dim3 grid(Bsz / 8, S);
        k_conv2<<<grid, 320, C2_SMEM_FLOATS * (int)sizeof(float)>>>();
    }
    // K4: fc1 + relu
    {
        dim3 grid(Bsz / 64, (500 + 63) / 64, S);
        k_fc1<<<grid, 256>>>();
    }
    // K5: fc2 logits
    {
        dim3 grid(Bsz, S);
        k_fc2<<<grid, 320>>>();
    }
    // K6: log_softmax + mean over samples
    k_reduce<<<Bsz, 128>>>(out);
}

// round 6
// speedup vs baseline: 1.1816x; 1.1816x over previous
#include <cuda_runtime.h>
#include <cuda_bf16.h>
#include <math.h>
#include <stdint.h>

#define S    100
#define Bsz  128
#define NW   430500
#define NB   580
#define NWB  431080
// weight offsets within a sample's NW block
#define W1_OFF 0        // [20][1][5][5]  = 500
#define W2_OFF 500      // [50][20][5][5] = 25000
#define W3_OFF 25500    // [500][800]     = 400000
#define W4_OFF 425500   // [10][500]      = 5000
// bias offsets
#define B1_OFF 0
#define B2_OFF 20
#define B3_OFF 70
#define B4_OFF 570

// ---------------- device scratch (allocation-free contract) ----------------
__device__ float g_w[(size_t)S * NW];          // only conv1/conv2/fc2 ranges filled
__device__ float g_b[(size_t)S * NB];
__device__ float g_spw[NW];
__device__ float g_spb[NB];
__device__ float g_h1[(size_t)S * Bsz * 20 * 12 * 12];
__device__ float g_h2[(size_t)S * Bsz * 800];
__device__ float g_h3[(size_t)S * Bsz * 500];
__device__ float g_logits[(size_t)Bsz * S * 10];

__device__ __forceinline__ uint32_t cvt_tf32(float f) {
    uint32_t r; asm("cvt.rna.tf32.f32 %0, %1;" : "=r"(r) : "f"(f)); return r;
}

// ---------------- K0: softplus precompute (once, not per-sample) -----------
__global__ void k_sp(const float* __restrict__ rho_w, const float* __restrict__ rho_b) {
    int i = blockIdx.x * 256 + threadIdx.x;
    if (i < NW) g_spw[i] = log1pf(expf(rho_w[i]));
    if (i < NB) g_spb[i] = log1pf(expf(rho_b[i]));
}

// ---------------- K1: materialize conv1/conv2/fc2 weights + all biases -----
__global__ void k_wgen(const float* __restrict__ e,
                       const float* __restrict__ mu_w, const float* __restrict__ mu_b) {
    int i = blockIdx.x * 256 + threadIdx.x;   // 0 .. 31079
    int s = blockIdx.y;
    if (i >= 31080) return;
    if (i < 30500) {
        int wi = (i < 25500) ? i : (i - 30500 + NW);   // conv1+conv2 | fc2 range
        g_w[(size_t)s * NW + wi] = fmaf(g_spw[wi], e[(size_t)s * NWB + wi], mu_w[wi]);
    } else {
        int j = i - 30500;
        g_b[s * NB + j] = fmaf(g_spb[j], e[(size_t)s * NWB + NW + j], mu_b[j]);
    }
}

// ---------------- K2: conv1 (1->20, 5x5) + relu + maxpool 2x2 --------------
__global__ void k_conv1(const float* __restrict__ x) {
    __shared__ __align__(16) float img[784];
    __shared__ float w1s[500];
    __shared__ float b1s[20];
    int b = blockIdx.x, s = blockIdx.y;
    int tid = threadIdx.x;
    const float* xim = x + (size_t)b * 784;
    for (int k = tid; k < 784; k += 256) img[k] = xim[k];
    const float* wp = g_w + (size_t)s * NW + W1_OFF;
    for (int k = tid; k < 500; k += 256) w1s[k] = wp[k];
    if (tid < 20) b1s[tid] = g_b[s * NB + B1_OFF + tid];
    __syncthreads();
    if (tid >= 240) return;
    int c = tid / 12, py = tid % 12;
    float wr[25];
#pragma unroll
    for (int k = 0; k < 25; k++) wr[k] = w1s[c * 25 + k];
    float p[12];
#pragma unroll
    for (int px = 0; px < 12; px++) p[px] = -1e30f;
#pragma unroll
    for (int dy = 0; dy < 2; dy++) {
        int y = 2 * py + dy;
        float acc[24];
#pragma unroll
        for (int xx = 0; xx < 24; xx++) acc[xx] = 0.f;
#pragma unroll
        for (int i = 0; i < 5; i++) {
            const float* row = &img[(y + i) * 28];
            float r[28];
#pragma unroll
            for (int q = 0; q < 7; q++) {
                float4 v = *(const float4*)&row[q * 4];
                r[q * 4 + 0] = v.x; r[q * 4 + 1] = v.y;
                r[q * 4 + 2] = v.z; r[q * 4 + 3] = v.w;
            }
#pragma unroll
            for (int j = 0; j < 5; j++) {
                float wv = wr[i * 5 + j];
#pragma unroll
                for (int xx = 0; xx < 24; xx++) acc[xx] = fmaf(wv, r[xx + j], acc[xx]);
            }
        }
#pragma unroll
        for (int px = 0; px < 12; px++)
            p[px] = fmaxf(p[px], fmaxf(acc[2 * px], acc[2 * px + 1]));
    }
    float bias = b1s[c];
    float* out = g_h1 + ((size_t)(s * Bsz + b) * 20 + c) * 144 + py * 12;
#pragma unroll
    for (int px = 0; px < 12; px++) out[px] = fmaxf(p[px] + bias, 0.f);
}

// ---------------- K3: conv2 (20->50, 5x5) + relu + maxpool 2x2 -------------
#define C2_SMEM_FLOATS (25000 + 56 + 4*2880 + 4*3200)
__global__ void k_conv2() {
    extern __shared__ __align__(16) float smem[];
    float* w2s = smem;
    float* b2s = smem + 25000;
    float* h1s = b2s + 56;
    float* cbuf = h1s + 4 * 2880;
    int s = blockIdx.y;
    int b0 = blockIdx.x * 8;
    int tid = threadIdx.x;
    const float* wp = g_w + (size_t)s * NW + W2_OFF;
    for (int k = tid; k < 25000; k += 320) w2s[k] = wp[k];
    if (tid < 50) b2s[tid] = g_b[s * NB + B2_OFF + tid];
    int il = tid / 80, r = tid % 80, cg = r / 8, y = r % 8;
    int c0 = cg * 5;
    for (int round = 0; round < 2; round++) {
        __syncthreads();
        for (int k = tid; k < 4 * 2880; k += 320) {
            int i2 = k / 2880, kk = k % 2880;
            h1s[k] = g_h1[(size_t)(s * Bsz + b0 + round * 4 + i2) * 2880 + kk];
        }
        __syncthreads();
        float acc[5][8];
#pragma unroll
        for (int c = 0; c < 5; c++)
#pragma unroll
            for (int xx = 0; xx < 8; xx++) acc[c][xx] = 0.f;
        const float* hin = &h1s[il * 2880];
        for (int ci = 0; ci < 20; ci++) {
#pragma unroll
            for (int i = 0; i < 5; i++) {
                const float* rp = &hin[ci * 144 + (y + i) * 12];
                float rin[12];
#pragma unroll
                for (int q = 0; q < 3; q++) {
                    float4 v = *(const float4*)&rp[q * 4];
                    rin[q * 4 + 0] = v.x; rin[q * 4 + 1] = v.y;
                    rin[q * 4 + 2] = v.z; rin[q * 4 + 3] = v.w;
                }
#pragma unroll
                for (int j = 0; j < 5; j++) {
#pragma unroll
                    for (int c = 0; c < 5; c++) {
                        float wv = w2s[((c0 + c) * 20 + ci) * 25 + i * 5 + j];
#pragma unroll
                        for (int xx = 0; xx < 8; xx++)
                            acc[c][xx] = fmaf(wv, rin[xx + j], acc[c][xx]);
                    }
                }
            }
        }
#pragma unroll
        for (int c = 0; c < 5; c++) {
            float bias = b2s[c0 + c];
#pragma unroll
            for (int xx = 0; xx < 8; xx++)
                cbuf[il * 3200 + (c0 + c) * 64 + y * 8 + xx] = fmaxf(acc[c][xx] + bias, 0.f);
        }
        __syncthreads();
        for (int k = tid; k < 4 * 800; k += 320) {
            int i2 = k / 800, q = k % 800;
            int c = q / 16, p = q % 16, py = p / 4, px = p % 4;
            const float* cb = &cbuf[i2 * 3200 + c * 64];
            float v = fmaxf(fmaxf(cb[(2 * py) * 8 + 2 * px],     cb[(2 * py) * 8 + 2 * px + 1]),
                            fmaxf(cb[(2 * py + 1) * 8 + 2 * px], cb[(2 * py + 1) * 8 + 2 * px + 1]));
            g_h2[(size_t)(s * Bsz + b0 + round * 4 + i2) * 800 + q] = v;
        }
    }
}

// ---------------- K4: fc1 (800->500) + relu via mma.sync tf32 --------------
// grid = (8 n-tiles of 64, S). 256 threads = 8 warps; warp w owns rows
// m0 = w*16 of the M=128 batch. K chunks of 32 staged in smem as tf32.
// w3 generated on the fly from mu + sp*e (never materialized).
// m16n8k8 fragment mapping per PTX ISA:
//   A: a0=[l/4][l%4] a1=[l/4+8][l%4] a2=[l/4][l%4+4] a3=[l/4+8][l%4+4]
//   B: b0=[k=l%4][n=l/4] b1=[k=l%4+4][n=l/4]
//   C: c0=[l/4][2(l%4)] c1=+1 c2=[l/4+8][2(l%4)] c3=+1
#define ASTR 36
__global__ __launch_bounds__(256) void k_fc1_mma(const float* __restrict__ e,
                                                 const float* __restrict__ mu_w) {
    __shared__ uint32_t As[128][ASTR];
    __shared__ uint32_t Bs[64][ASTR];
    int tid = threadIdx.x;
    int warp = tid >> 5, lane = tid & 31;
    int o0 = blockIdx.x * 64;
    int s  = blockIdx.y;
    int m0 = warp * 16;
    int lq = lane >> 2;        // lane/4
    int lr = lane & 3;         // lane%4

    const float* h2p = g_h2 + (size_t)s * Bsz * 800;
    const float* ep  = e + (size_t)s * NWB + W3_OFF;
    const float* mup = mu_w + W3_OFF;
    const float* spp = g_spw + W3_OFF;

    float c[8][4];
#pragma unroll
    for (int t = 0; t < 8; t++)
#pragma unroll
        for (int j = 0; j < 4; j++) c[t][j] = 0.f;

    for (int k0 = 0; k0 < 800; k0 += 32) {
        // stage A: 128x32 activations (1024 float4, 4 per thread)
#pragma unroll
        for (int i = 0; i < 4; i++) {
            int v = tid + 256 * i;
            int row = v >> 3, jj = v & 7;
            float4 a = *(const float4*)&h2p[row * 800 + k0 + jj * 4];
            As[row][jj * 4 + 0] = cvt_tf32(a.x);
            As[row][jj * 4 + 1] = cvt_tf32(a.y);
            As[row][jj * 4 + 2] = cvt_tf32(a.z);
            As[row][jj * 4 + 3] = cvt_tf32(a.w);
        }
        // stage B: 64x32 weights generated on the fly (512 float4, 2 per thread)
#pragma unroll
        for (int i = 0; i < 2; i++) {
            int v = tid + 256 * i;
            int row = v >> 3, jj = v & 7;
            int o = o0 + row;
            if (o < 500) {
                size_t gi = (size_t)o * 800 + k0 + jj * 4;
                float4 mu = *(const float4*)&mup[gi];
                float4 ee = *(const float4*)&ep[gi];
                float4 sp = *(const float4*)&spp[gi];
                Bs[row][jj * 4 + 0] = cvt_tf32(fmaf(sp.x, ee.x, mu.x));
                Bs[row][jj * 4 + 1] = cvt_tf32(fmaf(sp.y, ee.y, mu.y));
                Bs[row][jj * 4 + 2] = cvt_tf32(fmaf(sp.z, ee.z, mu.z));
                Bs[row][jj * 4 + 3] = cvt_tf32(fmaf(sp.w, ee.w, mu.w));
            } else {
                Bs[row][jj * 4 + 0] = 0u; Bs[row][jj * 4 + 1] = 0u;
                Bs[row][jj * 4 + 2] = 0u; Bs[row][jj * 4 + 3] = 0u;
            }
        }
        __syncthreads();
#pragma unroll
        for (int ks = 0; ks < 4; ks++) {
            int kk = ks * 8;
            uint32_t a0 = As[m0 + lq][kk + lr];
            uint32_t a1 = As[m0 + lq + 8][kk + lr];
            uint32_t a2 = As[m0 + lq][kk + lr + 4];
            uint32_t a3 = As[m0 + lq + 8][kk + lr + 4];
#pragma unroll
            for (int t = 0; t < 8; t++) {
                uint32_t b0 = Bs[t * 8 + lq][kk + lr];
                uint32_t b1 = Bs[t * 8 + lq][kk + lr + 4];
                asm volatile(
                    "mma.sync.aligned.m16n8k8.row.col.f32.tf32.tf32.f32 "
                    "{%0,%1,%2,%3}, {%4,%5,%6,%7}, {%8,%9}, {%0,%1,%2,%3};"
                    : "+f"(c[t][0]), "+f"(c[t][1]), "+f"(c[t][2]), "+f"(c[t][3])
                    : "r"(a0), "r"(a1), "r"(a2), "r"(a3), "r"(b0), "r"(b1));
            }
        }
        __syncthreads();
    }

    // epilogue: bias + relu, scatter to g_h3 [b][o]
    const float* bp = g_b + s * NB + B3_OFF;
    float* outp = g_h3 + (size_t)s * Bsz * 500;
    int brow0 = m0 + lq;
#pragma unroll
    for (int t = 0; t < 8; t++) {
        int o = o0 + t * 8 + lr * 2;
        if (o + 1 < 500) {
            float bi0 = bp[o], bi1 = bp[o + 1];
            float* p0 = &outp[(size_t)brow0 * 500 + o];
            p0[0] = fmaxf(c[t][0] + bi0, 0.f);
            p0[1] = fmaxf(c[t][1] + bi1, 0.f);
            float* p1 = &outp[(size_t)(brow0 + 8) * 500 + o];
            p1[0] = fmaxf(c[t][2] + bi0, 0.f);
            p1[1] = fmaxf(c[t][3] + bi1, 0.f);
        } else if (o < 500) {
            float bi0 = bp[o];
            outp[(size_t)brow0 * 500 + o]       = fmaxf(c[t][0] + bi0, 0.f);
            outp[(size_t)(brow0 + 8) * 500 + o] = fmaxf(c[t][2] + bi0, 0.f);
        }
    }
}

// ---------------- K5: fc2 (500 -> 10) logits -------------------------------
__global__ void k_fc2() {
    int b = blockIdx.x, s = blockIdx.y;
    int w = threadIdx.x / 32, lane = threadIdx.x % 32;
    const float* h3p = g_h3 + (size_t)(s * Bsz + b) * 500;
    const float* w4p = g_w + (size_t)s * NW + W4_OFF + w * 500;
    float sum = 0.f;
    for (int k = lane; k < 500; k += 32) sum = fmaf(h3p[k], w4p[k], sum);
#pragma unroll
    for (int off = 16; off > 0; off >>= 1)
        sum += __shfl_down_sync(0xFFFFFFFF, sum, off);
    if (lane == 0)
        g_logits[((size_t)b * S + s) * 10 + w] = sum + g_b[s * NB + B4_OFF + w];
}

// ---------------- K6: log_softmax over 10, mean over S ---------------------
__global__ void k_reduce(float* __restrict__ out) {
    __shared__ float red[128][10];
    int b = blockIdx.x;
    int tid = threadIdx.x;
    if (tid < S) {
        const float* lp = g_logits + ((size_t)b * S + tid) * 10;
        float l[10], m = -1e30f;
#pragma unroll
        for (int o = 0; o < 10; o++) { l[o] = lp[o]; m = fmaxf(m, l[o]); }
        float se = 0.f;
#pragma unroll
        for (int o = 0; o < 10; o++) se += expf(l[o] - m);
        float lse = m + logf(se);
#pragma unroll
        for (int o = 0; o < 10; o++) red[tid][o] = l[o] - lse;
    } else {
#pragma unroll
        for (int o = 0; o < 10; o++) red[tid][o] = 0.f;
    }
    __syncthreads();
    for (int st = 64; st >= 1; st >>= 1) {
        if (tid < st)
#pragma unroll
            for (int o = 0; o < 10; o++) red[tid][o] += red[tid + st][o];
        __syncthreads();
    }
    if (tid < 10) out[b * 10 + tid] = red[0][tid] * (1.f / S);
}

// ---------------- launch ----------------------------------------------------
extern "C" void kernel_launch(void* const* d_in, const int* in_sizes, int n_in,
                              void* d_out, int out_size) {
    const float* x     = (const float*)d_in[0];
    const float* e     = (const float*)d_in[1];
    const float* mu_w  = (const float*)d_in[2];
    const float* rho_w = (const float*)d_in[3];
    const float* mu_b  = (const float*)d_in[4];
    const float* rho_b = (const float*)d_in[5];
    float* out = (float*)d_out;

    // idempotent, called every time (no static guards per harness rules)
    cudaFuncSetAttribute(k_conv2, cudaFuncAttributeMaxDynamicSharedMemorySize,
                         C2_SMEM_FLOATS * (int)sizeof(float));

    // K0: softplus precompute (rho-only, sample-independent)
    k_sp<<<(NW + 255) / 256, 256>>>(rho_w, rho_b);
    // K1: materialize small weight ranges + biases (w3 never materialized)
    {
        dim3 grid((31080 + 255) / 256, S);
        k_wgen<<<grid, 256>>>(e, mu_w, mu_b);
    }
    // K2: conv1 + relu + pool
    {
        dim3 grid(Bsz, S);
        k_conv1<<<grid, 256>>>(x);
    }
    // K3: conv2 + relu + pool
    {
        dim3 grid(Bsz / 8, S);
        k_conv2<<<grid, 320, C2_SMEM_FLOATS * (int)sizeof(float)>>>();
    }
    // K4: fc1 + relu (mma.sync tf32, fused w3 generation)
    {
        dim3 grid(8, S);
        k_fc1_mma<<<grid, 256>>>(e, mu_w);
    }
    // K5: fc2 logits
    {
        dim3 grid(Bsz, S);
        k_fc2<<<grid, 320>>>();
    }
    // K6: log_softmax + mean over samples
    k_reduce<<<Bsz, 128>>>(out);
}

// round 12
// speedup vs baseline: 1.6077x; 1.3607x over previous
#include <cuda_runtime.h>
#include <cuda_bf16.h>
#include <math.h>
#include <stdint.h>

#define S    100
#define Bsz  128
#define NW   430500
#define NB   580
#define NWB  431080
// weight offsets within a sample's NW block
#define W1_OFF 0        // [20][1][5][5]  = 500
#define W2_OFF 500      // [50][20][5][5] = 25000
#define W3_OFF 25500    // [500][800]     = 400000
#define W4_OFF 425500   // [10][500]      = 5000
// bias offsets
#define B1_OFF 0
#define B2_OFF 20
#define B3_OFF 70
#define B4_OFF 570

// ---------------- device scratch (allocation-free contract) ----------------
__device__ float g_w[(size_t)S * NW];          // only conv1/conv2/fc2 ranges filled
__device__ float g_b[(size_t)S * NB];
__device__ float g_spw[NW];
__device__ float g_spb[NB];
__device__ float g_h1[(size_t)S * Bsz * 20 * 12 * 12];
__device__ float g_h2[(size_t)S * Bsz * 800];
__device__ float g_h3[(size_t)S * Bsz * 500];
__device__ float g_logits[(size_t)Bsz * S * 10];

__device__ __forceinline__ uint32_t cvt_tf32(float f) {
    uint32_t r; asm("cvt.rna.tf32.f32 %0, %1;" : "=r"(r) : "f"(f)); return r;
}

// ---------------- K0: softplus precompute (once, not per-sample) -----------
__global__ void k_sp(const float* __restrict__ rho_w, const float* __restrict__ rho_b) {
    int i = blockIdx.x * 256 + threadIdx.x;
    if (i < NW) g_spw[i] = log1pf(expf(rho_w[i]));
    if (i < NB) g_spb[i] = log1pf(expf(rho_b[i]));
}

// ---------------- K1: materialize conv1/conv2/fc2 weights + all biases -----
__global__ void k_wgen(const float* __restrict__ e,
                       const float* __restrict__ mu_w, const float* __restrict__ mu_b) {
    int i = blockIdx.x * 256 + threadIdx.x;   // 0 .. 31079
    int s = blockIdx.y;
    if (i >= 31080) return;
    if (i < 30500) {
        int wi = (i < 25500) ? i : (i - 30500 + NW);   // conv1+conv2 | fc2 range
        g_w[(size_t)s * NW + wi] = fmaf(g_spw[wi], e[(size_t)s * NWB + wi], mu_w[wi]);
    } else {
        int j = i - 30500;
        g_b[s * NB + j] = fmaf(g_spb[j], e[(size_t)s * NWB + NW + j], mu_b[j]);
    }
}

// ---------------- K2: conv1 (1->20, 5x5) + relu + maxpool 2x2 --------------
__global__ void k_conv1(const float* __restrict__ x) {
    __shared__ __align__(16) float img[784];
    __shared__ float w1s[500];
    __shared__ float b1s[20];
    int b = blockIdx.x, s = blockIdx.y;
    int tid = threadIdx.x;
    const float* xim = x + (size_t)b * 784;
    for (int k = tid; k < 784; k += 256) img[k] = xim[k];
    const float* wp = g_w + (size_t)s * NW + W1_OFF;
    for (int k = tid; k < 500; k += 256) w1s[k] = wp[k];
    if (tid < 20) b1s[tid] = g_b[s * NB + B1_OFF + tid];
    __syncthreads();
    if (tid >= 240) return;
    int c = tid / 12, py = tid % 12;
    float wr[25];
#pragma unroll
    for (int k = 0; k < 25; k++) wr[k] = w1s[c * 25 + k];
    float p[12];
#pragma unroll
    for (int px = 0; px < 12; px++) p[px] = -1e30f;
#pragma unroll
    for (int dy = 0; dy < 2; dy++) {
        int y = 2 * py + dy;
        float acc[24];
#pragma unroll
        for (int xx = 0; xx < 24; xx++) acc[xx] = 0.f;
#pragma unroll
        for (int i = 0; i < 5; i++) {
            const float* row = &img[(y + i) * 28];
            float r[28];
#pragma unroll
            for (int q = 0; q < 7; q++) {
                float4 v = *(const float4*)&row[q * 4];
                r[q * 4 + 0] = v.x; r[q * 4 + 1] = v.y;
                r[q * 4 + 2] = v.z; r[q * 4 + 3] = v.w;
            }
#pragma unroll
            for (int j = 0; j < 5; j++) {
                float wv = wr[i * 5 + j];
#pragma unroll
                for (int xx = 0; xx < 24; xx++) acc[xx] = fmaf(wv, r[xx + j], acc[xx]);
            }
        }
#pragma unroll
        for (int px = 0; px < 12; px++)
            p[px] = fmaxf(p[px], fmaxf(acc[2 * px], acc[2 * px + 1]));
    }
    float bias = b1s[c];
    float* out = g_h1 + ((size_t)(s * Bsz + b) * 20 + c) * 144 + py * 12;
#pragma unroll
    for (int px = 0; px < 12; px++) out[px] = fmaxf(p[px] + bias, 0.f);
}

// ---------------- K3: conv2 via mma.sync tf32 (implicit per-tap GEMM) ------
// Per block: 1 sample, 4 images, 256 threads = 8 warps (2 per image).
// Formulation per image: D[co 64][pix 64] = sum_{tap,ci} W[co][ci][tap] * h1T[pix_shift(tap)][ci]
//   A = weights, native [co][ci][i][j] layout (staged verbatim as tf32, 50 rows)
//   B = h1 transposed [pix 144][ci 20] (stride 20 -> conflict-free fragment LDS)
//   K = 20 -> ksteps {0,8,16}; k>=20 half-fragments zeroed at compile time.
// n-tile = output row y; c0/c1 = x-pair -> full 2x2 maxpool done in registers.
// 146.3 KB smem (R1 proved 197.5 KB opt-in works here); tap unroll capped for I$.
#define C2_IMGS 4
#define C2_THREADS (C2_IMGS * 64)
#define C2M_SMEM_BYTES ((25000 + 56 + C2_IMGS * 2880) * 4)
__global__ __launch_bounds__(C2_THREADS) void k_conv2_mma() {
    extern __shared__ __align__(16) unsigned char smraw[];
    uint32_t* wAs = (uint32_t*)smraw;                       // [50][20][25] tf32
    float*    b2s = (float*)(smraw + 25000 * 4);            // [56]
    uint32_t* hT  = (uint32_t*)(smraw + (25000 + 56) * 4);  // [C2_IMGS][144][20] tf32
    int s = blockIdx.y, b0 = blockIdx.x * C2_IMGS;
    int tid = threadIdx.x;

    const float* wp = g_w + (size_t)s * NW + W2_OFF;
    for (int k = tid; k < 25000; k += C2_THREADS) wAs[k] = cvt_tf32(wp[k]);
    if (tid < 50) b2s[tid] = g_b[s * NB + B2_OFF + tid];
    for (int k = tid; k < C2_IMGS * 2880; k += C2_THREADS) {
        int img = k / 2880, q = k % 2880;
        int ci = q / 144, pix = q % 144;
        hT[img * 2880 + pix * 20 + ci] =
            cvt_tf32(g_h1[(size_t)(s * Bsz + b0 + img) * 2880 + q]);
    }
    __syncthreads();

    int warp = tid >> 5, lane = tid & 31;
    int il = warp >> 1, half = warp & 1;
    int lq = lane >> 2, lr = lane & 3;
    const uint32_t* ht = hT + il * 2880;

    float c[2][8][4];
#pragma unroll
    for (int mt = 0; mt < 2; mt++)
#pragma unroll
        for (int nt = 0; nt < 8; nt++)
#pragma unroll
            for (int q = 0; q < 4; q++) c[mt][nt][q] = 0.f;

#pragma unroll 5
    for (int tap = 0; tap < 25; tap++) {
        int ti = tap / 5, tj = tap % 5;
#pragma unroll
        for (int ks = 0; ks < 3; ks++) {
            int kk = ks * 8;
            uint32_t bb0[8], bb1[8];
#pragma unroll
            for (int nt = 0; nt < 8; nt++) {
                int addr = ((nt + ti) * 12 + tj + lq) * 20 + kk + lr;
                bb0[nt] = ht[addr];
                bb1[nt] = (ks < 2) ? ht[addr + 4] : 0u;
            }
#pragma unroll
            for (int mt = 0; mt < 2; mt++) {
                int m0 = half * 32 + mt * 16;
                int r0 = m0 + lq, r1 = r0 + 8;
                uint32_t a0 = (r0 < 50) ? wAs[r0 * 500 + (kk + lr) * 25 + tap] : 0u;
                uint32_t a1 = (r1 < 50) ? wAs[r1 * 500 + (kk + lr) * 25 + tap] : 0u;
                uint32_t a2 = (ks < 2 && r0 < 50) ? wAs[r0 * 500 + (kk + lr + 4) * 25 + tap] : 0u;
                uint32_t a3 = (ks < 2 && r1 < 50) ? wAs[r1 * 500 + (kk + lr + 4) * 25 + tap] : 0u;
#pragma unroll
                for (int nt = 0; nt < 8; nt++) {
                    asm volatile(
                        "mma.sync.aligned.m16n8k8.row.col.f32.tf32.tf32.f32 "
                        "{%0,%1,%2,%3}, {%4,%5,%6,%7}, {%8,%9}, {%0,%1,%2,%3};"
                        : "+f"(c[mt][nt][0]), "+f"(c[mt][nt][1]),
                          "+f"(c[mt][nt][2]), "+f"(c[mt][nt][3])
                        : "r"(a0), "r"(a1), "r"(a2), "r"(a3),
                          "r"(bb0[nt]), "r"(bb1[nt]));
                }
            }
        }
    }

    // epilogue: 2x2 maxpool fully in registers, + bias + relu
    float* outp = g_h2 + (size_t)(s * Bsz + b0 + il) * 800;
#pragma unroll
    for (int mt = 0; mt < 2; mt++) {
        int m0 = half * 32 + mt * 16;
        int co_lo = m0 + lq, co_hi = co_lo + 8;
        float xlo[8], xhi[8];
#pragma unroll
        for (int nt = 0; nt < 8; nt++) {
            xlo[nt] = fmaxf(c[mt][nt][0], c[mt][nt][1]);   // x-pool, row co_lo, y=nt
            xhi[nt] = fmaxf(c[mt][nt][2], c[mt][nt][3]);   // x-pool, row co_hi, y=nt
        }
#pragma unroll
        for (int q = 0; q < 4; q++) {
            if (co_lo < 50) {
                float v = fmaxf(xlo[2 * q], xlo[2 * q + 1]);
                outp[co_lo * 16 + q * 4 + lr] = fmaxf(v + b2s[co_lo], 0.f);
            }
            if (co_hi < 50) {
                float v = fmaxf(xhi[2 * q], xhi[2 * q + 1]);
                outp[co_hi * 16 + q * 4 + lr] = fmaxf(v + b2s[co_hi], 0.f);
            }
        }
    }
}

// ---------------- K4: fc1 (800->500) + relu via mma.sync tf32 --------------
#define ASTR 36
__global__ __launch_bounds__(256) void k_fc1_mma(const float* __restrict__ e,
                                                 const float* __restrict__ mu_w) {
    __shared__ uint32_t As[128][ASTR];
    __shared__ uint32_t Bs[64][ASTR];
    int tid = threadIdx.x;
    int warp = tid >> 5, lane = tid & 31;
    int o0 = blockIdx.x * 64;
    int s  = blockIdx.y;
    int m0 = warp * 16;
    int lq = lane >> 2;
    int lr = lane & 3;

    const float* h2p = g_h2 + (size_t)s * Bsz * 800;
    const float* ep  = e + (size_t)s * NWB + W3_OFF;
    const float* mup = mu_w + W3_OFF;
    const float* spp = g_spw + W3_OFF;

    float c[8][4];
#pragma unroll
    for (int t = 0; t < 8; t++)
#pragma unroll
        for (int j = 0; j < 4; j++) c[t][j] = 0.f;

    for (int k0 = 0; k0 < 800; k0 += 32) {
#pragma unroll
        for (int i = 0; i < 4; i++) {
            int v = tid + 256 * i;
            int row = v >> 3, jj = v & 7;
            float4 a = *(const float4*)&h2p[row * 800 + k0 + jj * 4];
            As[row][jj * 4 + 0] = cvt_tf32(a.x);
            As[row][jj * 4 + 1] = cvt_tf32(a.y);
            As[row][jj * 4 + 2] = cvt_tf32(a.z);
            As[row][jj * 4 + 3] = cvt_tf32(a.w);
        }
#pragma unroll
        for (int i = 0; i < 2; i++) {
            int v = tid + 256 * i;
            int row = v >> 3, jj = v & 7;
            int o = o0 + row;
            if (o < 500) {
                size_t gi = (size_t)o * 800 + k0 + jj * 4;
                float4 mu = *(const float4*)&mup[gi];
                float4 ee = *(const float4*)&ep[gi];
                float4 sp = *(const float4*)&spp[gi];
                Bs[row][jj * 4 + 0] = cvt_tf32(fmaf(sp.x, ee.x, mu.x));
                Bs[row][jj * 4 + 1] = cvt_tf32(fmaf(sp.y, ee.y, mu.y));
                Bs[row][jj * 4 + 2] = cvt_tf32(fmaf(sp.z, ee.z, mu.z));
                Bs[row][jj * 4 + 3] = cvt_tf32(fmaf(sp.w, ee.w, mu.w));
            } else {
                Bs[row][jj * 4 + 0] = 0u; Bs[row][jj * 4 + 1] = 0u;
                Bs[row][jj * 4 + 2] = 0u; Bs[row][jj * 4 + 3] = 0u;
            }
        }
        __syncthreads();
#pragma unroll
        for (int ks = 0; ks < 4; ks++) {
            int kk = ks * 8;
            uint32_t a0 = As[m0 + lq][kk + lr];
            uint32_t a1 = As[m0 + lq + 8][kk + lr];
            uint32_t a2 = As[m0 + lq][kk + lr + 4];
            uint32_t a3 = As[m0 + lq + 8][kk + lr + 4];
#pragma unroll
            for (int t = 0; t < 8; t++) {
                uint32_t b0 = Bs[t * 8 + lq][kk + lr];
                uint32_t b1 = Bs[t * 8 + lq][kk + lr + 4];
                asm volatile(
                    "mma.sync.aligned.m16n8k8.row.col.f32.tf32.tf32.f32 "
                    "{%0,%1,%2,%3}, {%4,%5,%6,%7}, {%8,%9}, {%0,%1,%2,%3};"
                    : "+f"(c[t][0]), "+f"(c[t][1]), "+f"(c[t][2]), "+f"(c[t][3])
                    : "r"(a0), "r"(a1), "r"(a2), "r"(a3), "r"(b0), "r"(b1));
            }
        }
        __syncthreads();
    }

    const float* bp = g_b + s * NB + B3_OFF;
    float* outp = g_h3 + (size_t)s * Bsz * 500;
    int brow0 = m0 + lq;
#pragma unroll
    for (int t = 0; t < 8; t++) {
        int o = o0 + t * 8 + lr * 2;
        if (o + 1 < 500) {
            float bi0 = bp[o], bi1 = bp[o + 1];
            float* p0 = &outp[(size_t)brow0 * 500 + o];
            p0[0] = fmaxf(c[t][0] + bi0, 0.f);
            p0[1] = fmaxf(c[t][1] + bi1, 0.f);
            float* p1 = &outp[(size_t)(brow0 + 8) * 500 + o];
            p1[0] = fmaxf(c[t][2] + bi0, 0.f);
            p1[1] = fmaxf(c[t][3] + bi1, 0.f);
        } else if (o < 500) {
            float bi0 = bp[o];
            outp[(size_t)brow0 * 500 + o]       = fmaxf(c[t][0] + bi0, 0.f);
            outp[(size_t)(brow0 + 8) * 500 + o] = fmaxf(c[t][2] + bi0, 0.f);
        }
    }
}

// ---------------- K5: fc2 (500 -> 10) logits -------------------------------
__global__ void k_fc2() {
    int b = blockIdx.x, s = blockIdx.y;
    int w = threadIdx.x / 32, lane = threadIdx.x % 32;
    const float* h3p = g_h3 + (size_t)(s * Bsz + b) * 500;
    const float* w4p = g_w + (size_t)s * NW + W4_OFF + w * 500;
    float sum = 0.f;
    for (int k = lane; k < 500; k += 32) sum = fmaf(h3p[k], w4p[k], sum);
#pragma unroll
    for (int off = 16; off > 0; off >>= 1)
        sum += __shfl_down_sync(0xFFFFFFFF, sum, off);
    if (lane == 0)
        g_logits[((size_t)b * S + s) * 10 + w] = sum + g_b[s * NB + B4_OFF + w];
}

// ---------------- K6: log_softmax over 10, mean over S ---------------------
__global__ void k_reduce(float* __restrict__ out) {
    __shared__ float red[128][10];
    int b = blockIdx.x;
    int tid = threadIdx.x;
    if (tid < S) {
        const float* lp = g_logits + ((size_t)b * S + tid) * 10;
        float l[10], m = -1e30f;
#pragma unroll
        for (int o = 0; o < 10; o++) { l[o] = lp[o]; m = fmaxf(m, l[o]); }
        float se = 0.f;
#pragma unroll
        for (int o = 0; o < 10; o++) se += expf(l[o] - m);
        float lse = m + logf(se);
#pragma unroll
        for (int o = 0; o < 10; o++) red[tid][o] = l[o] - lse;
    } else {
#pragma unroll
        for (int o = 0; o < 10; o++) red[tid][o] = 0.f;
    }
    __syncthreads();
    for (int st = 64; st >= 1; st >>= 1) {
        if (tid < st)
#pragma unroll
            for (int o = 0; o < 10; o++) red[tid][o] += red[tid + st][o];
        __syncthreads();
    }
    if (tid < 10) out[b * 10 + tid] = red[0][tid] * (1.f / S);
}

// ---------------- launch ----------------------------------------------------
extern "C" void kernel_launch(void* const* d_in, const int* in_sizes, int n_in,
                              void* d_out, int out_size) {
    const float* x     = (const float*)d_in[0];
    const float* e     = (const float*)d_in[1];
    const float* mu_w  = (const float*)d_in[2];
    const float* rho_w = (const float*)d_in[3];
    const float* mu_b  = (const float*)d_in[4];
    const float* rho_b = (const float*)d_in[5];
    float* out = (float*)d_out;

    // idempotent, called every time (no static guards per harness rules)
    cudaFuncSetAttribute(k_conv2_mma, cudaFuncAttributeMaxDynamicSharedMemorySize,
                         C2M_SMEM_BYTES);

    // K0: softplus precompute (rho-only, sample-independent)
    k_sp<<<(NW + 255) / 256, 256>>>(rho_w, rho_b);
    // K1: materialize small weight ranges + biases (w3 never materialized)
    {
        dim3 grid((31080 + 255) / 256, S);
        k_wgen<<<grid, 256>>>(e, mu_w, mu_b);
    }
    // K2: conv1 + relu + pool
    {
        dim3 grid(Bsz, S);
        k_conv1<<<grid, 256>>>(x);
    }
    // K3: conv2 + relu + pool (tensor cores, fused pooling)
    {
        dim3 grid(Bsz / C2_IMGS, S);
        k_conv2_mma<<<grid, C2_THREADS, C2M_SMEM_BYTES>>>();
    }
    // K4: fc1 + relu (mma.sync tf32, fused w3 generation)
    {
        dim3 grid(8, S);
        k_fc1_mma<<<grid, 256>>>(e, mu_w);
    }
    // K5: fc2 logits
    {
        dim3 grid(Bsz, S);
        k_fc2<<<grid, 320>>>();
    }
    // K6: log_softmax + mean over samples
    k_reduce<<<Bsz, 128>>>(out);
}

// round 16
// speedup vs baseline: 2.0492x; 1.2746x over previous
#include <cuda_runtime.h>
#include <cuda_bf16.h>
#include <math.h>
#include <stdint.h>

#define S    100
#define Bsz  128
#define NW   430500
#define NB   580
#define NWB  431080
// weight offsets within a sample's NW block
#define W1_OFF 0        // [20][1][5][5]  = 500
#define W2_OFF 500      // [50][20][5][5] = 25000
#define W3_OFF 25500    // [500][800]     = 400000
#define W4_OFF 425500   // [10][500]      = 5000
// bias offsets
#define B1_OFF 0
#define B2_OFF 20
#define B3_OFF 70
#define B4_OFF 570

// ---------------- device scratch (allocation-free contract) ----------------
__device__ float g_w[(size_t)S * NW];          // only conv1/conv2/fc2 ranges filled
__device__ float g_b[(size_t)S * NB];
__device__ float g_spw[NW];
__device__ float g_spb[NB];
__device__ float g_h1[(size_t)S * Bsz * 20 * 12 * 12];
__device__ float g_h2[(size_t)S * Bsz * 800];
__device__ float g_h3[(size_t)S * Bsz * 500];
__device__ float g_logits[(size_t)Bsz * S * 10];

__device__ __forceinline__ uint32_t cvt_tf32(float f) {
    uint32_t r; asm("cvt.rna.tf32.f32 %0, %1;" : "=r"(r) : "f"(f)); return r;
}

// ---------------- K0: softplus precompute (once, not per-sample) -----------
__global__ void k_sp(const float* __restrict__ rho_w, const float* __restrict__ rho_b) {
    int i = blockIdx.x * 256 + threadIdx.x;
    if (i < NW) g_spw[i] = log1pf(expf(rho_w[i]));
    if (i < NB) g_spb[i] = log1pf(expf(rho_b[i]));
}

// ---------------- K1: materialize conv1/conv2/fc2 weights + all biases -----
__global__ void k_wgen(const float* __restrict__ e,
                       const float* __restrict__ mu_w, const float* __restrict__ mu_b) {
    int i = blockIdx.x * 256 + threadIdx.x;   // 0 .. 31079
    int s = blockIdx.y;
    if (i >= 31080) return;
    if (i < 30500) {
        int wi = (i < 25500) ? i : (i - 30500 + NW);   // conv1+conv2 | fc2 range
        g_w[(size_t)s * NW + wi] = fmaf(g_spw[wi], e[(size_t)s * NWB + wi], mu_w[wi]);
    } else {
        int j = i - 30500;
        g_b[s * NB + j] = fmaf(g_spb[j], e[(size_t)s * NWB + NW + j], mu_b[j]);
    }
}

// ---------------- K2: conv1 (1->20, 5x5) + relu + maxpool 2x2 --------------
__global__ void k_conv1(const float* __restrict__ x) {
    __shared__ __align__(16) float img[784];
    __shared__ float w1s[500];
    __shared__ float b1s[20];
    int b = blockIdx.x, s = blockIdx.y;
    int tid = threadIdx.x;
    const float* xim = x + (size_t)b * 784;
    for (int k = tid; k < 784; k += 256) img[k] = xim[k];
    const float* wp = g_w + (size_t)s * NW + W1_OFF;
    for (int k = tid; k < 500; k += 256) w1s[k] = wp[k];
    if (tid < 20) b1s[tid] = g_b[s * NB + B1_OFF + tid];
    __syncthreads();
    if (tid >= 240) return;
    int c = tid / 12, py = tid % 12;
    float wr[25];
#pragma unroll
    for (int k = 0; k < 25; k++) wr[k] = w1s[c * 25 + k];
    float p[12];
#pragma unroll
    for (int px = 0; px < 12; px++) p[px] = -1e30f;
#pragma unroll
    for (int dy = 0; dy < 2; dy++) {
        int y = 2 * py + dy;
        float acc[24];
#pragma unroll
        for (int xx = 0; xx < 24; xx++) acc[xx] = 0.f;
#pragma unroll
        for (int i = 0; i < 5; i++) {
            const float* row = &img[(y + i) * 28];
            float r[28];
#pragma unroll
            for (int q = 0; q < 7; q++) {
                float4 v = *(const float4*)&row[q * 4];
                r[q * 4 + 0] = v.x; r[q * 4 + 1] = v.y;
                r[q * 4 + 2] = v.z; r[q * 4 + 3] = v.w;
            }
#pragma unroll
            for (int j = 0; j < 5; j++) {
                float wv = wr[i * 5 + j];
#pragma unroll
                for (int xx = 0; xx < 24; xx++) acc[xx] = fmaf(wv, r[xx + j], acc[xx]);
            }
        }
#pragma unroll
        for (int px = 0; px < 12; px++)
            p[px] = fmaxf(p[px], fmaxf(acc[2 * px], acc[2 * px + 1]));
    }
    float bias = b1s[c];
    float* out = g_h1 + ((size_t)(s * Bsz + b) * 20 + c) * 144 + py * 12;
#pragma unroll
    for (int px = 0; px < 12; px++) out[px] = fmaxf(p[px] + bias, 0.f);
}

// ---------------- K3: conv2 via mma.sync tf32 (implicit per-tap GEMM) ------
// Per block: 1 sample, 8 images, 512 threads = 16 warps (2 per image).
// Doubled warps/SM vs R12 (occ 12.4% -> ~25%) to cover HMMA+LDS latency;
// smem 192.4 KB (R1 proved 197.5 KB opt-in works). Tap unroll capped for I$
// (R10 timeout attributed to full-unroll pathology).
#define C2_IMGS 8
#define C2_THREADS (C2_IMGS * 64)
#define C2M_SMEM_BYTES ((25000 + 56 + C2_IMGS * 2880) * 4)
__global__ __launch_bounds__(C2_THREADS) void k_conv2_mma() {
    extern __shared__ __align__(16) unsigned char smraw[];
    uint32_t* wAs = (uint32_t*)smraw;                       // [50][20][25] tf32
    float*    b2s = (float*)(smraw + 25000 * 4);            // [56]
    uint32_t* hT  = (uint32_t*)(smraw + (25000 + 56) * 4);  // [C2_IMGS][144][20] tf32
    int s = blockIdx.y, b0 = blockIdx.x * C2_IMGS;
    int tid = threadIdx.x;

    const float* wp = g_w + (size_t)s * NW + W2_OFF;
    for (int k = tid; k < 25000; k += C2_THREADS) wAs[k] = cvt_tf32(wp[k]);
    if (tid < 50) b2s[tid] = g_b[s * NB + B2_OFF + tid];
    for (int k = tid; k < C2_IMGS * 2880; k += C2_THREADS) {
        int img = k / 2880, q = k % 2880;
        int ci = q / 144, pix = q % 144;
        hT[img * 2880 + pix * 20 + ci] =
            cvt_tf32(g_h1[(size_t)(s * Bsz + b0 + img) * 2880 + q]);
    }
    __syncthreads();

    int warp = tid >> 5, lane = tid & 31;
    int il = warp >> 1, half = warp & 1;
    int lq = lane >> 2, lr = lane & 3;
    const uint32_t* ht = hT + il * 2880;

    float c[2][8][4];
#pragma unroll
    for (int mt = 0; mt < 2; mt++)
#pragma unroll
        for (int nt = 0; nt < 8; nt++)
#pragma unroll
            for (int q = 0; q < 4; q++) c[mt][nt][q] = 0.f;

#pragma unroll 5
    for (int tap = 0; tap < 25; tap++) {
        int ti = tap / 5, tj = tap % 5;
#pragma unroll
        for (int ks = 0; ks < 3; ks++) {
            int kk = ks * 8;
            uint32_t bb0[8], bb1[8];
#pragma unroll
            for (int nt = 0; nt < 8; nt++) {
                int addr = ((nt + ti) * 12 + tj + lq) * 20 + kk + lr;
                bb0[nt] = ht[addr];
                bb1[nt] = (ks < 2) ? ht[addr + 4] : 0u;
            }
#pragma unroll
            for (int mt = 0; mt < 2; mt++) {
                int m0 = half * 32 + mt * 16;
                int r0 = m0 + lq, r1 = r0 + 8;
                uint32_t a0 = (r0 < 50) ? wAs[r0 * 500 + (kk + lr) * 25 + tap] : 0u;
                uint32_t a1 = (r1 < 50) ? wAs[r1 * 500 + (kk + lr) * 25 + tap] : 0u;
                uint32_t a2 = (ks < 2 && r0 < 50) ? wAs[r0 * 500 + (kk + lr + 4) * 25 + tap] : 0u;
                uint32_t a3 = (ks < 2 && r1 < 50) ? wAs[r1 * 500 + (kk + lr + 4) * 25 + tap] : 0u;
#pragma unroll
                for (int nt = 0; nt < 8; nt++) {
                    asm volatile(
                        "mma.sync.aligned.m16n8k8.row.col.f32.tf32.tf32.f32 "
                        "{%0,%1,%2,%3}, {%4,%5,%6,%7}, {%8,%9}, {%0,%1,%2,%3};"
                        : "+f"(c[mt][nt][0]), "+f"(c[mt][nt][1]),
                          "+f"(c[mt][nt][2]), "+f"(c[mt][nt][3])
                        : "r"(a0), "r"(a1), "r"(a2), "r"(a3),
                          "r"(bb0[nt]), "r"(bb1[nt]));
                }
            }
        }
    }

    // epilogue: 2x2 maxpool fully in registers, + bias + relu
    float* outp = g_h2 + (size_t)(s * Bsz + b0 + il) * 800;
#pragma unroll
    for (int mt = 0; mt < 2; mt++) {
        int m0 = half * 32 + mt * 16;
        int co_lo = m0 + lq, co_hi = co_lo + 8;
        float xlo[8], xhi[8];
#pragma unroll
        for (int nt = 0; nt < 8; nt++) {
            xlo[nt] = fmaxf(c[mt][nt][0], c[mt][nt][1]);   // x-pool, row co_lo, y=nt
            xhi[nt] = fmaxf(c[mt][nt][2], c[mt][nt][3]);   // x-pool, row co_hi, y=nt
        }
#pragma unroll
        for (int q = 0; q < 4; q++) {
            if (co_lo < 50) {
                float v = fmaxf(xlo[2 * q], xlo[2 * q + 1]);
                outp[co_lo * 16 + q * 4 + lr] = fmaxf(v + b2s[co_lo], 0.f);
            }
            if (co_hi < 50) {
                float v = fmaxf(xhi[2 * q], xhi[2 * q + 1]);
                outp[co_hi * 16 + q * 4 + lr] = fmaxf(v + b2s[co_hi], 0.f);
            }
        }
    }
}

// ---------------- K4: fc1 (800->500) + relu via mma.sync tf32 --------------
#define ASTR 36
__global__ __launch_bounds__(256) void k_fc1_mma(const float* __restrict__ e,
                                                 const float* __restrict__ mu_w) {
    __shared__ uint32_t As[128][ASTR];
    __shared__ uint32_t Bs[64][ASTR];
    int tid = threadIdx.x;
    int warp = tid >> 5, lane = tid & 31;
    int o0 = blockIdx.x * 64;
    int s  = blockIdx.y;
    int m0 = warp * 16;
    int lq = lane >> 2;
    int lr = lane & 3;

    const float* h2p = g_h2 + (size_t)s * Bsz * 800;
    const float* ep  = e + (size_t)s * NWB + W3_OFF;
    const float* mup = mu_w + W3_OFF;
    const float* spp = g_spw + W3_OFF;

    float c[8][4];
#pragma unroll
    for (int t = 0; t < 8; t++)
#pragma unroll
        for (int j = 0; j < 4; j++) c[t][j] = 0.f;

    for (int k0 = 0; k0 < 800; k0 += 32) {
#pragma unroll
        for (int i = 0; i < 4; i++) {
            int v = tid + 256 * i;
            int row = v >> 3, jj = v & 7;
            float4 a = *(const float4*)&h2p[row * 800 + k0 + jj * 4];
            As[row][jj * 4 + 0] = cvt_tf32(a.x);
            As[row][jj * 4 + 1] = cvt_tf32(a.y);
            As[row][jj * 4 + 2] = cvt_tf32(a.z);
            As[row][jj * 4 + 3] = cvt_tf32(a.w);
        }
#pragma unroll
        for (int i = 0; i < 2; i++) {
            int v = tid + 256 * i;
            int row = v >> 3, jj = v & 7;
            int o = o0 + row;
            if (o < 500) {
                size_t gi = (size_t)o * 800 + k0 + jj * 4;
                float4 mu = *(const float4*)&mup[gi];
                float4 ee = *(const float4*)&ep[gi];
                float4 sp = *(const float4*)&spp[gi];
                Bs[row][jj * 4 + 0] = cvt_tf32(fmaf(sp.x, ee.x, mu.x));
                Bs[row][jj * 4 + 1] = cvt_tf32(fmaf(sp.y, ee.y, mu.y));
                Bs[row][jj * 4 + 2] = cvt_tf32(fmaf(sp.z, ee.z, mu.z));
                Bs[row][jj * 4 + 3] = cvt_tf32(fmaf(sp.w, ee.w, mu.w));
            } else {
                Bs[row][jj * 4 + 0] = 0u; Bs[row][jj * 4 + 1] = 0u;
                Bs[row][jj * 4 + 2] = 0u; Bs[row][jj * 4 + 3] = 0u;
            }
        }
        __syncthreads();
#pragma unroll
        for (int ks = 0; ks < 4; ks++) {
            int kk = ks * 8;
            uint32_t a0 = As[m0 + lq][kk + lr];
            uint32_t a1 = As[m0 + lq + 8][kk + lr];
            uint32_t a2 = As[m0 + lq][kk + lr + 4];
            uint32_t a3 = As[m0 + lq + 8][kk + lr + 4];
#pragma unroll
            for (int t = 0; t < 8; t++) {
                uint32_t b0 = Bs[t * 8 + lq][kk + lr];
                uint32_t b1 = Bs[t * 8 + lq][kk + lr + 4];
                asm volatile(
                    "mma.sync.aligned.m16n8k8.row.col.f32.tf32.tf32.f32 "
                    "{%0,%1,%2,%3}, {%4,%5,%6,%7}, {%8,%9}, {%0,%1,%2,%3};"
                    : "+f"(c[t][0]), "+f"(c[t][1]), "+f"(c[t][2]), "+f"(c[t][3])
                    : "r"(a0), "r"(a1), "r"(a2), "r"(a3), "r"(b0), "r"(b1));
            }
        }
        __syncthreads();
    }

    const float* bp = g_b + s * NB + B3_OFF;
    float* outp = g_h3 + (size_t)s * Bsz * 500;
    int brow0 = m0 + lq;
#pragma unroll
    for (int t = 0; t < 8; t++) {
        int o = o0 + t * 8 + lr * 2;
        if (o + 1 < 500) {
            float bi0 = bp[o], bi1 = bp[o + 1];
            float* p0 = &outp[(size_t)brow0 * 500 + o];
            p0[0] = fmaxf(c[t][0] + bi0, 0.f);
            p0[1] = fmaxf(c[t][1] + bi1, 0.f);
            float* p1 = &outp[(size_t)(brow0 + 8) * 500 + o];
            p1[0] = fmaxf(c[t][2] + bi0, 0.f);
            p1[1] = fmaxf(c[t][3] + bi1, 0.f);
        } else if (o < 500) {
            float bi0 = bp[o];
            outp[(size_t)brow0 * 500 + o]       = fmaxf(c[t][0] + bi0, 0.f);
            outp[(size_t)(brow0 + 8) * 500 + o] = fmaxf(c[t][2] + bi0, 0.f);
        }
    }
}

// ---------------- K5: fc2 (500 -> 10) logits -------------------------------
__global__ void k_fc2() {
    int b = blockIdx.x, s = blockIdx.y;
    int w = threadIdx.x / 32, lane = threadIdx.x % 32;
    const float* h3p = g_h3 + (size_t)(s * Bsz + b) * 500;
    const float* w4p = g_w + (size_t)s * NW + W4_OFF + w * 500;
    float sum = 0.f;
    for (int k = lane; k < 500; k += 32) sum = fmaf(h3p[k], w4p[k], sum);
#pragma unroll
    for (int off = 16; off > 0; off >>= 1)
        sum += __shfl_down_sync(0xFFFFFFFF, sum, off);
    if (lane == 0)
        g_logits[((size_t)b * S + s) * 10 + w] = sum + g_b[s * NB + B4_OFF + w];
}

// ---------------- K6: log_softmax over 10, mean over S ---------------------
__global__ void k_reduce(float* __restrict__ out) {
    __shared__ float red[128][10];
    int b = blockIdx.x;
    int tid = threadIdx.x;
    if (tid < S) {
        const float* lp = g_logits + ((size_t)b * S + tid) * 10;
        float l[10], m = -1e30f;
#pragma unroll
        for (int o = 0; o < 10; o++) { l[o] = lp[o]; m = fmaxf(m, l[o]); }
        float se = 0.f;
#pragma unroll
        for (int o = 0; o < 10; o++) se += expf(l[o] - m);
        float lse = m + logf(se);
#pragma unroll
        for (int o = 0; o < 10; o++) red[tid][o] = l[o] - lse;
    } else {
#pragma unroll
        for (int o = 0; o < 10; o++) red[tid][o] = 0.f;
    }
    __syncthreads();
    for (int st = 64; st >= 1; st >>= 1) {
        if (tid < st)
#pragma unroll
            for (int o = 0; o < 10; o++) red[tid][o] += red[tid + st][o];
        __syncthreads();
    }
    if (tid < 10) out[b * 10 + tid] = red[0][tid] * (1.f / S);
}

// ---------------- launch ----------------------------------------------------
extern "C" void kernel_launch(void* const* d_in, const int* in_sizes, int n_in,
                              void* d_out, int out_size) {
    const float* x     = (const float*)d_in[0];
    const float* e     = (const float*)d_in[1];
    const float* mu_w  = (const float*)d_in[2];
    const float* rho_w = (const float*)d_in[3];
    const float* mu_b  = (const float*)d_in[4];
    const float* rho_b = (const float*)d_in[5];
    float* out = (float*)d_out;

    // idempotent, called every time (no static guards per harness rules)
    cudaFuncSetAttribute(k_conv2_mma, cudaFuncAttributeMaxDynamicSharedMemorySize,
                         C2M_SMEM_BYTES);

    // K0: softplus precompute (rho-only, sample-independent)
    k_sp<<<(NW + 255) / 256, 256>>>(rho_w, rho_b);
    // K1: materialize small weight ranges + biases (w3 never materialized)
    {
        dim3 grid((31080 + 255) / 256, S);
        k_wgen<<<grid, 256>>>(e, mu_w, mu_b);
    }
    // K2: conv1 + relu + pool
    {
        dim3 grid(Bsz, S);
        k_conv1<<<grid, 256>>>(x);
    }
    // K3: conv2 + relu + pool (tensor cores, fused pooling)
    {
        dim3 grid(Bsz / C2_IMGS, S);
        k_conv2_mma<<<grid, C2_THREADS, C2M_SMEM_BYTES>>>();
    }
    // K4: fc1 + relu (mma.sync tf32, fused w3 generation)
    {
        dim3 grid(8, S);
        k_fc1_mma<<<grid, 256>>>(e, mu_w);
    }
    // K5: fc2 logits
    {
        dim3 grid(Bsz, S);
        k_fc2<<<grid, 320>>>();
    }
    // K6: log_softmax + mean over samples
    k_reduce<<<Bsz, 128>>>(out);
}